// round 1
// baseline (speedup 1.0000x reference)
#include <cuda_runtime.h>

#define NB 4
#define NC 128
#define NH 256
#define NW 512
#define ND 64

#define W_TILE 64
#define THREADS 256

// SMEM: cost tile [ND][W_TILE] + h1 tile [NC][W_TILE + ND]
#define COST_S_FLOATS (ND * W_TILE)          // 4096
#define H1_ROW_FLOATS (W_TILE + ND)          // 128
#define H1_S_FLOATS   (NC * H1_ROW_FLOATS)   // 16384
#define SMEM_BYTES ((COST_S_FLOATS + H1_S_FLOATS) * 4)  // 81920

// 16B-chunk XOR swizzle: kills the wg vs wg+4 (q vs q+8) 2-way bank conflict
// while keeping every co-issued chunk set {k + 2*wg} distinct mod 8.
__device__ __forceinline__ int swz(int q) { return q ^ ((q >> 3) & 1); }

__global__ void __launch_bounds__(THREADS, 2)
corr_kernel(const float* __restrict__ h1,
            const float* __restrict__ cost,
            float* __restrict__ out)
{
    extern __shared__ float smem[];
    float* cost_s = smem;                    // [ND][16 chunks], swizzled rows
    float* h1_s   = smem + COST_S_FLOATS;    // [NC][32 chunks], swizzled rows

    const int wt = blockIdx.x;   // w-tile 0..7
    const int hh = blockIdx.y;   // 0..255
    const int bb = blockIdx.z;   // 0..3
    const int w0 = wt * W_TILE;

    const int tid  = threadIdx.x;
    const int warp = tid >> 5;
    const int lane = tid & 31;

    // ---- Load h1 tile: rows [0..127] of 128 floats (w0 .. w0+127, zero-padded past NW).
    // One warp per 16 rows; lane = 16B chunk within row. Global coalesced (512B/row),
    // SMEM conflict-free (each quarter-warp hits 8 distinct bank groups via swz).
    {
        const size_t gbase = (((size_t)bb * NC) * NH + hh) * NW;
        #pragma unroll
        for (int j = 0; j < 16; j++) {
            const int row = warp * 16 + j;           // c
            const int gw  = w0 + lane * 4;
            float4 v = make_float4(0.f, 0.f, 0.f, 0.f);
            if (gw < NW)
                v = *(const float4*)(h1 + gbase + (size_t)row * (NH * NW) + gw);
            *(float4*)(h1_s + row * H1_ROW_FLOATS + swz(lane) * 4) = v;
        }
    }

    // ---- Load cost tile: rows [0..63] of 64 floats. Half-warp per row.
    {
        const size_t gbase = (((size_t)bb * ND) * NH + hh) * NW + w0;
        #pragma unroll
        for (int j = 0; j < 4; j++) {
            const int row  = warp * 8 + j * 2 + (lane >> 4);  // d
            const int cidx = lane & 15;                       // chunk 0..15
            float4 v = *(const float4*)(cost + gbase + (size_t)row * (NH * NW) + cidx * 4);
            *(float4*)(cost_s + row * W_TILE + swz(cidx) * 4) = v;
        }
    }

    __syncthreads();

    // ---- Compute: thread = (cg, wg); covers 4 channels x 8 consecutive w.
    const int wg = tid & 7;
    const int cg = tid >> 3;
    const int wb = wg * 8;          // w offset in tile
    const int cb = cg * 4;          // channel base
    const int qb = wg * 2;          // 16B-chunk base of this thread's w window

    float acc[4][8];
    #pragma unroll
    for (int c = 0; c < 4; c++)
        #pragma unroll
        for (int w = 0; w < 8; w++) acc[c][w] = 0.f;

    #pragma unroll
    for (int d0 = 0; d0 < ND; d0 += 4) {
        // h1 window per channel: floats [wb+d0, wb+d0+11] -> 3 swizzled chunks
        float hv[4][12];
        #pragma unroll
        for (int c = 0; c < 4; c++) {
            const float* hrow = h1_s + (cb + c) * H1_ROW_FLOATS;
            #pragma unroll
            for (int j = 0; j < 3; j++) {
                const int q = qb + (d0 >> 2) + j;
                float4 v = *(const float4*)(hrow + swz(q) * 4);
                hv[c][j * 4 + 0] = v.x;
                hv[c][j * 4 + 1] = v.y;
                hv[c][j * 4 + 2] = v.z;
                hv[c][j * 4 + 3] = v.w;
            }
        }
        #pragma unroll
        for (int dd = 0; dd < 4; dd++) {
            const float* crow = cost_s + (d0 + dd) * W_TILE;
            float4 c0 = *(const float4*)(crow + swz(qb + 0) * 4);
            float4 c1 = *(const float4*)(crow + swz(qb + 1) * 4);
            float cr[8] = {c0.x, c0.y, c0.z, c0.w, c1.x, c1.y, c1.z, c1.w};
            #pragma unroll
            for (int c = 0; c < 4; c++)
                #pragma unroll
                for (int w = 0; w < 8; w++)
                    acc[c][w] = fmaf(cr[w], hv[c][dd + w], acc[c][w]);
        }
    }

    // ---- Store
    {
        const size_t obase = (((size_t)bb * NC + cb) * NH + hh) * NW + w0 + wb;
        #pragma unroll
        for (int c = 0; c < 4; c++) {
            float* op = out + obase + (size_t)c * (NH * NW);
            *(float4*)(op)     = make_float4(acc[c][0], acc[c][1], acc[c][2], acc[c][3]);
            *(float4*)(op + 4) = make_float4(acc[c][4], acc[c][5], acc[c][6], acc[c][7]);
        }
    }
}

extern "C" void kernel_launch(void* const* d_in, const int* in_sizes, int n_in,
                              void* d_out, int out_size)
{
    const float* h1   = (const float*)d_in[0];
    const float* cost = (const float*)d_in[1];
    float* out        = (float*)d_out;

    // Idempotent; legal during graph capture (not a stream op).
    cudaFuncSetAttribute(corr_kernel, cudaFuncAttributeMaxDynamicSharedMemorySize, SMEM_BYTES);

    dim3 grid(NW / W_TILE, NH, NB);
    corr_kernel<<<grid, THREADS, SMEM_BYTES>>>(h1, cost, out);
}

// round 2
// speedup vs baseline: 1.0041x; 1.0041x over previous
#include <cuda_runtime.h>

#define NB 4
#define NC 128
#define NH 256
#define NW 512
#define ND 64

#define W_TILE 64
#define THREADS 256

// SMEM: cost tile [ND][W_TILE] + h1 tile [NC][W_TILE + ND]
#define COST_S_FLOATS (ND * W_TILE)          // 4096
#define H1_ROW_FLOATS (W_TILE + ND)          // 128 floats = 32 x 16B chunks
#define H1_S_FLOATS   (NC * H1_ROW_FLOATS)   // 16384
#define SMEM_BYTES ((COST_S_FLOATS + H1_S_FLOATS) * 4)  // 81920

// 16B-chunk XOR swizzle: spreads the 8 wg-chunks across all 8 bank groups.
__device__ __forceinline__ int swz(int q) { return q ^ ((q >> 3) & 1); }

__global__ void __launch_bounds__(THREADS, 2)
corr_kernel(const float* __restrict__ h1,
            const float* __restrict__ cost,
            float* __restrict__ out)
{
    extern __shared__ float smem[];
    float* cost_s = smem;                    // [ND][16 chunks], swizzled rows
    float* h1_s   = smem + COST_S_FLOATS;    // [NC][32 chunks], swizzled rows

    const int wt = blockIdx.x;   // w-tile 0..7
    const int hh = blockIdx.y;   // 0..255
    const int bb = blockIdx.z;   // 0..3
    const int w0 = wt * W_TILE;

    const int tid  = threadIdx.x;
    const int warp = tid >> 5;
    const int lane = tid & 31;

    // ---- Load h1 tile: 128 rows x 128 floats (w0 .. w0+127, zero past NW).
    {
        const size_t gbase = (((size_t)bb * NC) * NH + hh) * NW;
        #pragma unroll
        for (int j = 0; j < 16; j++) {
            const int row = warp * 16 + j;           // c
            const int gw  = w0 + lane * 4;
            float4 v = make_float4(0.f, 0.f, 0.f, 0.f);
            if (gw < NW)
                v = *(const float4*)(h1 + gbase + (size_t)row * (NH * NW) + gw);
            *(float4*)(h1_s + row * H1_ROW_FLOATS + swz(lane) * 4) = v;
        }
    }

    // ---- Load cost tile: 64 rows x 64 floats. Half-warp per row.
    {
        const size_t gbase = (((size_t)bb * ND) * NH + hh) * NW + w0;
        #pragma unroll
        for (int j = 0; j < 4; j++) {
            const int row  = warp * 8 + j * 2 + (lane >> 4);  // d
            const int cidx = lane & 15;                       // chunk 0..15
            float4 v = *(const float4*)(cost + gbase + (size_t)row * (NH * NW) + cidx * 4);
            *(float4*)(cost_s + row * W_TILE + swz(cidx) * 4) = v;
        }
    }

    __syncthreads();

    // ---- Compute: thread = (cg, wg); 4 channels x 8 consecutive w.
    const int wg = tid & 7;
    const int cg = tid >> 3;
    const int wb = wg * 8;          // w offset in tile
    const int cb = cg * 4;          // channel base
    const int qb = wg * 2;          // 16B-chunk base of this thread's w window

    float acc[4][8];
    #pragma unroll
    for (int c = 0; c < 4; c++)
        #pragma unroll
        for (int w = 0; w < 8; w++) acc[c][w] = 0.f;

    // Rolling register window of h1: 3 chunks (12 floats) per channel.
    // At iteration k (d0 = 4k), slot (k+co)%3 holds chunk qb+k+co for co=0..2,
    // i.e. floats [wb + 4k + 4*co ...]. Fully unrolled -> pure register renaming.
    float hv[4][3][4];
    const float* hrow[4];
    #pragma unroll
    for (int c = 0; c < 4; c++) {
        hrow[c] = h1_s + (cb + c) * H1_ROW_FLOATS;
        #pragma unroll
        for (int j = 0; j < 3; j++) {
            float4 v = *(const float4*)(hrow[c] + swz(qb + j) * 4);
            hv[c][j][0] = v.x; hv[c][j][1] = v.y; hv[c][j][2] = v.z; hv[c][j][3] = v.w;
        }
    }

    #pragma unroll
    for (int k = 0; k < ND / 4; k++) {          // d0 = 4k
        #pragma unroll
        for (int dd = 0; dd < 4; dd++) {
            const float* crow = cost_s + (4 * k + dd) * W_TILE;
            float4 c0 = *(const float4*)(crow + swz(qb + 0) * 4);
            float4 c1 = *(const float4*)(crow + swz(qb + 1) * 4);
            float cr[8] = {c0.x, c0.y, c0.z, c0.w, c1.x, c1.y, c1.z, c1.w};
            #pragma unroll
            for (int c = 0; c < 4; c++) {
                #pragma unroll
                for (int w = 0; w < 8; w++) {
                    const int f  = dd + w;            // 0..10, offset in window
                    const int co = f >> 2;            // chunk within window
                    const int fi = f & 3;
                    acc[c][w] = fmaf(cr[w], hv[c][(k + co) % 3][fi], acc[c][w]);
                }
            }
        }
        // Prefetch chunk qb+k+3 into the slot just freed (slot k%3).
        if (k < ND / 4 - 1) {
            #pragma unroll
            for (int c = 0; c < 4; c++) {
                float4 v = *(const float4*)(hrow[c] + swz(qb + k + 3) * 4);
                hv[c][k % 3][0] = v.x; hv[c][k % 3][1] = v.y;
                hv[c][k % 3][2] = v.z; hv[c][k % 3][3] = v.w;
            }
        }
    }

    // ---- Store
    {
        const size_t obase = (((size_t)bb * NC + cb) * NH + hh) * NW + w0 + wb;
        #pragma unroll
        for (int c = 0; c < 4; c++) {
            float* op = out + obase + (size_t)c * (NH * NW);
            *(float4*)(op)     = make_float4(acc[c][0], acc[c][1], acc[c][2], acc[c][3]);
            *(float4*)(op + 4) = make_float4(acc[c][4], acc[c][5], acc[c][6], acc[c][7]);
        }
    }
}

extern "C" void kernel_launch(void* const* d_in, const int* in_sizes, int n_in,
                              void* d_out, int out_size)
{
    const float* h1   = (const float*)d_in[0];
    const float* cost = (const float*)d_in[1];
    float* out        = (float*)d_out;

    cudaFuncSetAttribute(corr_kernel, cudaFuncAttributeMaxDynamicSharedMemorySize, SMEM_BYTES);

    dim3 grid(NW / W_TILE, NH, NB);
    corr_kernel<<<grid, THREADS, SMEM_BYTES>>>(h1, cost, out);
}

// round 4
// speedup vs baseline: 1.3237x; 1.3183x over previous
#include <cuda_runtime.h>
#include <cuda_bf16.h>
#include <cstdint>

#define NB 4
#define NC 128
#define NH 256
#define NW 512
#define ND 64
#define W_TILE 64
#define THREADS 256

// SMEM (bytes): bf16 tiles, rows of 128 elements = 256B (16 chunks of 16B).
// Chunk-XOR swizzle: chunk' = chunk ^ (row & 7)  -> ldmatrix conflict-free.
#define SM_AHI  0                       // A_hi [128m x 128k] bf16 (32KB)
#define SM_ALO  (SM_AHI + 32768)        // A_lo (32KB)
#define SM_BHI  (SM_ALO + 32768)        // B_hi [64n x 128k] bf16 (16KB)
#define SM_BLO  (SM_BHI + 16384)        // B_lo (16KB)
#define SMEM_TOTAL (SM_BLO + 16384)     // 98304 -> 2 CTAs/SM

__device__ __forceinline__ uint32_t smem_u32(const void* p) {
    uint32_t a;
    asm("{ .reg .u64 t; cvta.to.shared.u64 t, %1; cvt.u32.u64 %0, t; }" : "=r"(a) : "l"(p));
    return a;
}
// byte offset of element (row, k) in a swizzled tile (row stride 256B)
__device__ __forceinline__ uint32_t tile_off(int row, int k) {
    return (uint32_t)(row * 256 + (((k >> 3) ^ (row & 7)) << 4) + (k & 7) * 2);
}
__device__ __forceinline__ void bsplit(float x, uint16_t& hi, uint16_t& lo) {
    __nv_bfloat16 h = __float2bfloat16(x);
    __nv_bfloat16 l = __float2bfloat16(x - __bfloat162float(h));
    hi = *reinterpret_cast<uint16_t*>(&h);
    lo = *reinterpret_cast<uint16_t*>(&l);
}
__device__ __forceinline__ void ldsm4(uint32_t* r, uint32_t addr) {
    asm volatile("ldmatrix.sync.aligned.m8n8.x4.shared.b16 {%0,%1,%2,%3}, [%4];"
                 : "=r"(r[0]), "=r"(r[1]), "=r"(r[2]), "=r"(r[3]) : "r"(addr));
}
__device__ __forceinline__ void mma16816(float* c, const uint32_t* a, const uint32_t* b) {
    asm volatile("mma.sync.aligned.m16n8k16.row.col.f32.bf16.bf16.f32 "
                 "{%0,%1,%2,%3}, {%4,%5,%6,%7}, {%8,%9}, {%0,%1,%2,%3};"
                 : "+f"(c[0]), "+f"(c[1]), "+f"(c[2]), "+f"(c[3])
                 : "r"(a[0]), "r"(a[1]), "r"(a[2]), "r"(a[3]), "r"(b[0]), "r"(b[1]));
}

__global__ void __launch_bounds__(THREADS, 2)
corr_mma_kernel(const float* __restrict__ h1,
                const float* __restrict__ cost,
                float* __restrict__ out)
{
    extern __shared__ char smem[];
    const uint32_t smb = smem_u32(smem);
    const int tid  = threadIdx.x;
    const int wid  = tid >> 5;
    const int lane = tid & 31;

    const int wt = blockIdx.x;   // 0..7
    const int hh = blockIdx.y;   // 0..255
    const int bb = blockIdx.z;   // 0..3
    const int w0 = wt * W_TILE;

    // ---- Phase 1: zero B (32KB), load+split A, fetch cost into registers ----
    {
        uint4 z = make_uint4(0, 0, 0, 0);
        #pragma unroll
        for (int j = 0; j < 8; j++)
            *reinterpret_cast<uint4*>(smem + SM_BHI + (j * THREADS + tid) * 16) = z;
    }
    {
        #pragma unroll
        for (int j = 0; j < 16; j++) {
            const int idx = j * THREADS + tid;
            const int row = idx >> 5;          // c
            const int q   = idx & 31;          // float4 within row
            const int gw  = w0 + q * 4;
            float4 v = make_float4(0.f, 0.f, 0.f, 0.f);
            if (gw < NW)
                v = *reinterpret_cast<const float4*>(
                        h1 + (((size_t)bb * NC + row) * NH + hh) * NW + gw);
            uint16_t ha, la, hb2, lb, hc, lc, hd, ld;
            bsplit(v.x, ha, la); bsplit(v.y, hb2, lb);
            bsplit(v.z, hc, lc); bsplit(v.w, hd, ld);
            uint2 hp, lp;
            hp.x = (uint32_t)ha | ((uint32_t)hb2 << 16);
            hp.y = (uint32_t)hc | ((uint32_t)hd << 16);
            lp.x = (uint32_t)la | ((uint32_t)lb << 16);
            lp.y = (uint32_t)lc | ((uint32_t)ld << 16);
            const uint32_t off = tile_off(row, q * 4);   // 8B aligned (q*4 elems)
            *reinterpret_cast<uint2*>(smem + SM_AHI + off) = hp;
            *reinterpret_cast<uint2*>(smem + SM_ALO + off) = lp;
        }
    }
    // cost: 4096 floats -> 16 per thread (4 float4), kept in registers across the sync
    float4 cv[4];
    int cd[4], cw[4];
    {
        #pragma unroll
        for (int j = 0; j < 4; j++) {
            const int idx = j * THREADS + tid;
            cd[j] = idx >> 4;          // d
            cw[j] = (idx & 15) * 4;    // w base
            cv[j] = *reinterpret_cast<const float4*>(
                        cost + (((size_t)bb * ND + cd[j]) * NH + hh) * NW + w0 + cw[j]);
        }
    }
    __syncthreads();

    // ---- Phase 2: shear-scatter cost into B: B[w][w+d] = cost[d][w] ----
    {
        #pragma unroll
        for (int j = 0; j < 4; j++) {
            const float x[4] = {cv[j].x, cv[j].y, cv[j].z, cv[j].w};
            #pragma unroll
            for (int e = 0; e < 4; e++) {
                const int w = cw[j] + e;
                const uint32_t off = tile_off(w, w + cd[j]);
                uint16_t hi, lo;
                bsplit(x[e], hi, lo);
                *reinterpret_cast<uint16_t*>(smem + SM_BHI + off) = hi;
                *reinterpret_cast<uint16_t*>(smem + SM_BLO + off) = lo;
            }
        }
    }
    __syncthreads();

    // ---- Phase 3: warp-tile GEMM. Warp = 32m x 32n; 8 warps cover 128x64 ----
    const int m_warp = (wid & 3) * 32;
    const int n_warp = (wid >> 2) * 32;
    const int qd = lane >> 2;    // quad row 0..7
    const int tq = lane & 3;

    // ldmatrix lane-address components
    const int sub  = lane >> 3;       // 0..3
    const int rid  = lane & 7;
    const int a_m  = (sub & 1) * 8 + rid;    // + mt*16 + m_warp
    const int a_ks = (sub >> 1);             // k half (chunks)
    const int b_n  = (sub >> 1) * 8 + rid;   // + pair*16 + n_warp
    const int b_ks = (sub & 1);

    float acc[2][4][4];
    #pragma unroll
    for (int mt = 0; mt < 2; mt++)
        #pragma unroll
        for (int nt = 0; nt < 4; nt++)
            #pragma unroll
            for (int e = 0; e < 4; e++) acc[mt][nt][e] = 0.f;

    #pragma unroll
    for (int ks = 0; ks < 8; ks++) {          // k16 steps
        uint32_t ahi[2][4], alo[2][4], bhi[2][4], blo[2][4];
        #pragma unroll
        for (int mt = 0; mt < 2; mt++) {
            const int m = m_warp + mt * 16 + a_m;
            const uint32_t off = (uint32_t)(m * 256 + (((ks * 2 + a_ks) ^ (m & 7)) << 4));
            ldsm4(ahi[mt], smb + SM_AHI + off);
            ldsm4(alo[mt], smb + SM_ALO + off);
        }
        #pragma unroll
        for (int p = 0; p < 2; p++) {         // each x4 covers two n8 tiles
            const int n = n_warp + p * 16 + b_n;
            const uint32_t off = (uint32_t)(n * 256 + (((ks * 2 + b_ks) ^ (n & 7)) << 4));
            ldsm4(bhi[p], smb + SM_BHI + off);
            ldsm4(blo[p], smb + SM_BLO + off);
        }
        #pragma unroll
        for (int mt = 0; mt < 2; mt++) {
            #pragma unroll
            for (int nt = 0; nt < 4; nt++) {
                const uint32_t* bh = &bhi[nt >> 1][(nt & 1) * 2];
                const uint32_t* bl = &blo[nt >> 1][(nt & 1) * 2];
                mma16816(acc[mt][nt], ahi[mt], bh);
                mma16816(acc[mt][nt], ahi[mt], bl);
                mma16816(acc[mt][nt], alo[mt], bh);
            }
        }
    }

    // ---- Epilogue: register fragments -> gmem (float2 stores) ----
    {
        #pragma unroll
        for (int mt = 0; mt < 2; mt++) {
            const int m0 = m_warp + mt * 16 + qd;
            float* r0 = out + (((size_t)bb * NC + m0) * NH + hh) * NW + w0 + n_warp;
            float* r1 = out + (((size_t)bb * NC + m0 + 8) * NH + hh) * NW + w0 + n_warp;
            #pragma unroll
            for (int nt = 0; nt < 4; nt++) {
                const int nc2 = nt * 8 + tq * 2;
                *reinterpret_cast<float2*>(r0 + nc2) = make_float2(acc[mt][nt][0], acc[mt][nt][1]);
                *reinterpret_cast<float2*>(r1 + nc2) = make_float2(acc[mt][nt][2], acc[mt][nt][3]);
            }
        }
    }
}

extern "C" void kernel_launch(void* const* d_in, const int* in_sizes, int n_in,
                              void* d_out, int out_size)
{
    const float* h1   = (const float*)d_in[0];
    const float* cost = (const float*)d_in[1];
    float* out        = (float*)d_out;

    cudaFuncSetAttribute(corr_mma_kernel, cudaFuncAttributeMaxDynamicSharedMemorySize, SMEM_TOTAL);

    dim3 grid(NW / W_TILE, NH, NB);
    corr_mma_kernel<<<grid, THREADS, SMEM_TOTAL>>>(h1, cost, out);
}

// round 5
// speedup vs baseline: 1.4771x; 1.1159x over previous
#include <cuda_runtime.h>
#include <cuda_bf16.h>
#include <cstdint>

#define NB 4
#define NC 128
#define NH 256
#define NW 512
#define ND 64
#define W_TILE 64
#define THREADS 256

// SMEM (bytes): bf16 tiles, rows of 128 elements = 256B (16 chunks of 16B).
// Chunk-XOR swizzle: chunk' = chunk ^ (row & 7)  -> ldmatrix conflict-free.
#define SM_AHI  0                       // A_hi [128m x 128k] bf16 (32KB)
#define SM_ALO  (SM_AHI + 32768)        // A_lo (32KB)
#define SM_BHI  (SM_ALO + 32768)        // B_hi [64n x 128k] bf16 (16KB)
#define SM_BLO  (SM_BHI + 16384)        // B_lo (16KB)
#define SMEM_TOTAL (SM_BLO + 16384)     // 98304 -> 2 CTAs/SM

__device__ __forceinline__ uint32_t smem_u32(const void* p) {
    uint32_t a;
    asm("{ .reg .u64 t; cvta.to.shared.u64 t, %1; cvt.u32.u64 %0, t; }" : "=r"(a) : "l"(p));
    return a;
}
__device__ __forceinline__ uint32_t tile_off(int row, int k) {
    return (uint32_t)(row * 256 + (((k >> 3) ^ (row & 7)) << 4) + (k & 7) * 2);
}
__device__ __forceinline__ void bsplit(float x, uint16_t& hi, uint16_t& lo) {
    __nv_bfloat16 h = __float2bfloat16(x);
    __nv_bfloat16 l = __float2bfloat16(x - __bfloat162float(h));
    hi = *reinterpret_cast<uint16_t*>(&h);
    lo = *reinterpret_cast<uint16_t*>(&l);
}
__device__ __forceinline__ void ldsm4(uint32_t* r, uint32_t addr) {
    asm volatile("ldmatrix.sync.aligned.m8n8.x4.shared.b16 {%0,%1,%2,%3}, [%4];"
                 : "=r"(r[0]), "=r"(r[1]), "=r"(r[2]), "=r"(r[3]) : "r"(addr));
}
__device__ __forceinline__ void mma16816(float* c, const uint32_t* a, const uint32_t* b) {
    asm volatile("mma.sync.aligned.m16n8k16.row.col.f32.bf16.bf16.f32 "
                 "{%0,%1,%2,%3}, {%4,%5,%6,%7}, {%8,%9}, {%0,%1,%2,%3};"
                 : "+f"(c[0]), "+f"(c[1]), "+f"(c[2]), "+f"(c[3])
                 : "r"(a[0]), "r"(a[1]), "r"(a[2]), "r"(a[3]), "r"(b[0]), "r"(b[1]));
}

// Band-pruned mainloop, specialized on the warp's n offset (0 or 32).
// B[w][k] nonzero iff k-w in [0,64). For n8 tile at nb: nonzero k in [nb, nb+70].
template <int NWARP>
__device__ __forceinline__ void mainloop(uint32_t smb, int m_warp,
                                         int a_m, int a_ks, int b_n, int b_ks,
                                         float acc[2][4][4])
{
    #pragma unroll
    for (int ks = 0; ks < 8; ks++) {
        const bool needA = (ks >= NWARP / 16) && (ks <= NWARP / 16 + 5);
        if (!needA) continue;
        uint32_t ahi[2][4], alo[2][4], bhi[2][4], blo[2][4];
        #pragma unroll
        for (int mt = 0; mt < 2; mt++) {
            const int m = m_warp + mt * 16 + a_m;
            const uint32_t off = (uint32_t)(m * 256 + (((ks * 2 + a_ks) ^ (m & 7)) << 4));
            ldsm4(ahi[mt], smb + SM_AHI + off);
            ldsm4(alo[mt], smb + SM_ALO + off);
        }
        #pragma unroll
        for (int p = 0; p < 2; p++) {
            const bool needB = (ks >= NWARP / 16 + p) && (ks <= NWARP / 16 + p + 4);
            if (!needB) continue;
            const int n = NWARP + p * 16 + b_n;
            const uint32_t off = (uint32_t)(n * 256 + (((ks * 2 + b_ks) ^ (n & 7)) << 4));
            ldsm4(bhi[p], smb + SM_BHI + off);
            ldsm4(blo[p], smb + SM_BLO + off);
        }
        #pragma unroll
        for (int mt = 0; mt < 2; mt++) {
            #pragma unroll
            for (int nt = 0; nt < 4; nt++) {
                const int nb = NWARP + nt * 8;
                const bool use = (16 * ks <= nb + 70) && (16 * ks + 15 >= nb);
                if (!use) continue;
                const uint32_t* bh = &bhi[nt >> 1][(nt & 1) * 2];
                const uint32_t* bl = &blo[nt >> 1][(nt & 1) * 2];
                mma16816(acc[mt][nt], ahi[mt], bh);
                mma16816(acc[mt][nt], ahi[mt], bl);
                mma16816(acc[mt][nt], alo[mt], bh);
            }
        }
    }
}

__global__ void __launch_bounds__(THREADS, 2)
corr_mma_kernel(const float* __restrict__ h1,
                const float* __restrict__ cost,
                float* __restrict__ out)
{
    extern __shared__ char smem[];
    const uint32_t smb = smem_u32(smem);
    const int tid  = threadIdx.x;
    const int wid  = tid >> 5;
    const int lane = tid & 31;

    const int wt = blockIdx.x;   // 0..7
    const int hh = blockIdx.y;   // 0..255
    const int bb = blockIdx.z;   // 0..3
    const int w0 = wt * W_TILE;

    // ---- Phase 1: zero B (32KB), load+split A, fetch cost into registers ----
    {
        uint4 z = make_uint4(0, 0, 0, 0);
        #pragma unroll
        for (int j = 0; j < 8; j++)
            *reinterpret_cast<uint4*>(smem + SM_BHI + (j * THREADS + tid) * 16) = z;
    }
    {
        #pragma unroll
        for (int j = 0; j < 16; j++) {
            const int idx = j * THREADS + tid;
            const int row = idx >> 5;          // c
            const int q   = idx & 31;          // float4 within row
            const int gw  = w0 + q * 4;
            float4 v = make_float4(0.f, 0.f, 0.f, 0.f);
            if (gw < NW)
                v = *reinterpret_cast<const float4*>(
                        h1 + (((size_t)bb * NC + row) * NH + hh) * NW + gw);
            uint16_t ha, la, hb2, lb, hc, lc, hd, ld;
            bsplit(v.x, ha, la); bsplit(v.y, hb2, lb);
            bsplit(v.z, hc, lc); bsplit(v.w, hd, ld);
            uint2 hp, lp;
            hp.x = (uint32_t)ha | ((uint32_t)hb2 << 16);
            hp.y = (uint32_t)hc | ((uint32_t)hd << 16);
            lp.x = (uint32_t)la | ((uint32_t)lb << 16);
            lp.y = (uint32_t)lc | ((uint32_t)ld << 16);
            const uint32_t off = tile_off(row, q * 4);
            *reinterpret_cast<uint2*>(smem + SM_AHI + off) = hp;
            *reinterpret_cast<uint2*>(smem + SM_ALO + off) = lp;
        }
    }
    float4 cv[4];
    int cd[4], cw[4];
    {
        #pragma unroll
        for (int j = 0; j < 4; j++) {
            const int idx = j * THREADS + tid;
            cd[j] = idx >> 4;          // d
            cw[j] = (idx & 15) * 4;    // w base
            cv[j] = *reinterpret_cast<const float4*>(
                        cost + (((size_t)bb * ND + cd[j]) * NH + hh) * NW + w0 + cw[j]);
        }
    }
    __syncthreads();

    // ---- Phase 2: shear-scatter cost into B: B[w][w+d] = cost[d][w] ----
    {
        #pragma unroll
        for (int j = 0; j < 4; j++) {
            const float x[4] = {cv[j].x, cv[j].y, cv[j].z, cv[j].w};
            #pragma unroll
            for (int e = 0; e < 4; e++) {
                const int w = cw[j] + e;
                const uint32_t off = tile_off(w, w + cd[j]);
                uint16_t hi, lo;
                bsplit(x[e], hi, lo);
                *reinterpret_cast<uint16_t*>(smem + SM_BHI + off) = hi;
                *reinterpret_cast<uint16_t*>(smem + SM_BLO + off) = lo;
            }
        }
    }
    __syncthreads();

    // ---- Phase 3: warp-tile GEMM. Warp = 32m x 32n; band-pruned K ----
    const int m_warp = (wid & 3) * 32;
    const int n_warp = (wid >> 2) * 32;
    const int qd = lane >> 2;
    const int tq = lane & 3;

    const int sub  = lane >> 3;
    const int rid  = lane & 7;
    const int a_m  = (sub & 1) * 8 + rid;
    const int a_ks = (sub >> 1);
    const int b_n  = (sub >> 1) * 8 + rid;
    const int b_ks = (sub & 1);

    float acc[2][4][4];
    #pragma unroll
    for (int mt = 0; mt < 2; mt++)
        #pragma unroll
        for (int nt = 0; nt < 4; nt++)
            #pragma unroll
            for (int e = 0; e < 4; e++) acc[mt][nt][e] = 0.f;

    if (n_warp == 0)
        mainloop<0>(smb, m_warp, a_m, a_ks, b_n, b_ks, acc);
    else
        mainloop<32>(smb, m_warp, a_m, a_ks, b_n, b_ks, acc);

    // ---- Epilogue ----
    {
        #pragma unroll
        for (int mt = 0; mt < 2; mt++) {
            const int m0 = m_warp + mt * 16 + qd;
            float* r0 = out + (((size_t)bb * NC + m0) * NH + hh) * NW + w0 + n_warp;
            float* r1 = out + (((size_t)bb * NC + m0 + 8) * NH + hh) * NW + w0 + n_warp;
            #pragma unroll
            for (int nt = 0; nt < 4; nt++) {
                const int nc2 = nt * 8 + tq * 2;
                *reinterpret_cast<float2*>(r0 + nc2) = make_float2(acc[mt][nt][0], acc[mt][nt][1]);
                *reinterpret_cast<float2*>(r1 + nc2) = make_float2(acc[mt][nt][2], acc[mt][nt][3]);
            }
        }
    }
}

extern "C" void kernel_launch(void* const* d_in, const int* in_sizes, int n_in,
                              void* d_out, int out_size)
{
    const float* h1   = (const float*)d_in[0];
    const float* cost = (const float*)d_in[1];
    float* out        = (float*)d_out;

    cudaFuncSetAttribute(corr_mma_kernel, cudaFuncAttributeMaxDynamicSharedMemorySize, SMEM_TOTAL);

    dim3 grid(NW / W_TILE, NH, NB);
    corr_mma_kernel<<<grid, THREADS, SMEM_TOTAL>>>(h1, cost, out);
}